// round 17
// baseline (speedup 1.0000x reference)
#include <cuda_runtime.h>
#include <math.h>

typedef unsigned long long u64;
#define DEV __device__ __forceinline__

// ---- packed f32x2 helpers (sm_103a) ----
DEV u64 ffma2(u64 a, u64 b, u64 c) { u64 d; asm("fma.rn.f32x2 %0,%1,%2,%3;" : "=l"(d) : "l"(a), "l"(b), "l"(c)); return d; }
DEV u64 pk2(float x, float y) { u64 d; asm("mov.b64 %0,{%1,%2};" : "=l"(d) : "f"(x), "f"(y)); return d; }
DEV float2 upk(u64 v) { float2 r; asm("mov.b64 {%0,%1},%2;" : "=f"(r.x), "=f"(r.y) : "l"(v)); return r; }
DEV float hadd(u64 v) { float2 f = upk(v); return f.x + f.y; }
DEV u64 ldsh(const float2& p) { return *reinterpret_cast<const u64*>(&p); }
DEV float gelu_exact(float v) { return 0.5f * v * (1.0f + erff(v * 0.70710678118654752f)); }

// ---- fixed problem shape (B,T,H,W)=(2,15,192,192), C=P=16 ----
constexpr int T_   = 15;
constexpr int C_   = 16;
constexpr int KP   = 8;           // pairs of 16
constexpr int HW_  = 192 * 192;   // 36864
constexpr int B_   = 2;
constexpr int NSEQ = B_ * HW_;    // 73728
constexpr int BLK  = 128;
constexpr float EPS_ = 1e-5f;
constexpr float INV2PI = 0.15915494309189535f;

__global__ void __launch_bounds__(BLK, 5) ssm_kernel(
    const float* __restrict__ x,
    const float* __restrict__ w_in, const float* __restrict__ b_in,
    const float* __restrict__ ag,   const float* __restrict__ ab,
    const float* __restrict__ Lre,  const float* __restrict__ Lim,
    const float* __restrict__ Bre,  const float* __restrict__ Bim,
    const float* __restrict__ Cre,  const float* __restrict__ Cim,
    const float* __restrict__ Dv,   const float* __restrict__ lstep,
    const float* __restrict__ ffg,  const float* __restrict__ ffb,
    const float* __restrict__ We,   const float* __restrict__ Wd,
    const float* __restrict__ og,   const float* __restrict__ ob,
    const float* __restrict__ Wo,   const float* __restrict__ bo,
    float* __restrict__ out)
{
    // folded SSM tables: sM[j][k] = {M1[j][2k], M1[j][2k+1], M2[j][2k], M2[j][2k+1]}
    __shared__ float4 sM[T_][KP];
    __shared__ float  sK3[C_];
    // precompute scratch
    __shared__ float2 sLam[T_][C_];                       // Lambda_bar^j per p
    __shared__ float  sP1r[C_], sP1i[C_], sP2r[C_], sP2i[C_], sQ3r[C_], sQ3i[C_], sMask[C_];
    // weights as float4 rows
    __shared__ float4 sWe4[2 * C_][4], sWd4[C_][4], sWo4[C_][4];
    __shared__ float sWc[C_], sBc[C_], sG1[C_], sB1[C_], sD[C_];
    __shared__ float sFfg[C_], sFfb[C_], sOg[C_], sOb[C_], sBo[C_];
    __shared__ float sVarA, sVarB2, sVarC;

    const int tid = threadIdx.x;

    // ---- cooperative weight loads (256 float4 over 128 threads) ----
    #pragma unroll
    for (int s = tid; s < 256; s += BLK) {
        if (s < 128)      ((float4*)sWe4)[s]       = ((const float4*)We)[s];
        else if (s < 192) ((float4*)sWd4)[s - 128] = ((const float4*)Wd)[s - 128];
        else              ((float4*)sWo4)[s - 192] = ((const float4*)Wo)[s - 192];
    }

    // ---- stage 1: per-p constants (16 threads) ----
    if (tid < 16) {
        const int p = tid;
        float mw = 0.f, mb = 0.f;
        #pragma unroll
        for (int c = 0; c < C_; c++) { mw += w_in[c]; mb += b_in[c]; }
        mw *= (1.f / C_); mb *= (1.f / C_);

        float step = expf(lstep[p]);
        float ar = Lre[p], ai = Lim[p];
        float ea = expf(ar * step);
        float lr = ea * cosf(ai * step);
        float li = ea * sinf(ai * step);

        // coef = (Lam_bar - 1)/Lam
        float inv = 1.f / (ar * ar + ai * ai);
        float cr = ((lr - 1.f) * ar + li * ai) * inv;
        float ci = (li * ar - (lr - 1.f) * ai) * inv;

        float p1r = 0.f, p1i = 0.f, p2r = 0.f, p2i = 0.f, p3r = 0.f, p3i = 0.f;
        #pragma unroll
        for (int c = 0; c < C_; c++) {
            float br = Bre[p * C_ + c], bi = Bim[p * C_ + c];
            float rr = cr * br - ci * bi;
            float ri = cr * bi + ci * br;
            float gg = ag[c];
            float wc = (w_in[c] - mw) * gg;
            float bc = (b_in[c] - mb) * gg;
            float be = ab[c];
            p1r = fmaf(wc, rr, p1r); p1i = fmaf(wc, ri, p1i);
            p2r = fmaf(bc, rr, p2r); p2i = fmaf(bc, ri, p2i);
            p3r = fmaf(be, rr, p3r); p3i = fmaf(be, ri, p3i);
        }
        sP1r[p] = p1r; sP1i[p] = p1i;
        sP2r[p] = p2r; sP2i[p] = p2i;

        // Lambda_bar^j table + S = sum_j Lam_bar^j
        float srr = 0.f, sii = 0.f, cR = 1.f, cI = 0.f;
        #pragma unroll
        for (int j = 0; j < T_; j++) {
            sLam[j][p] = make_float2(cR, cI);
            srr += cR; sii += cI;
            float nR = cR * lr - cI * li;
            cI = cR * li + cI * lr;
            cR = nR;
        }
        sQ3r[p] = p3r * srr - p3i * sii;
        sQ3i[p] = p3r * sii + p3i * srr;

        sMask[p] = (step * fabsf(ai) * INV2PI) < 0.25f ? 1.f : 0.f;

        sWc[p] = w_in[p] - mw;  sBc[p] = b_in[p] - mb;
        sG1[p] = ag[p];  sB1[p] = ab[p];  sD[p] = Dv[p];
        sFfg[p] = ffg[p]; sFfb[p] = ffb[p];
        sOg[p] = og[p];  sOb[p] = ob[p];  sBo[p] = bo[p];

        if (p == 0) {
            float A = 0.f, Bs = 0.f, Cs = 0.f;
            #pragma unroll
            for (int c = 0; c < C_; c++) {
                float wc2 = w_in[c] - mw, bc2 = b_in[c] - mb;
                A += wc2 * wc2; Bs += wc2 * bc2; Cs += bc2 * bc2;
            }
            sVarA = A * (1.f / C_); sVarB2 = 2.f * Bs * (1.f / C_); sVarC = Cs * (1.f / C_);
        }
    }
    __syncthreads();

    // ---- stage 2: fold C through -> real M1/M2 tables + K3 (256 items / 128 thr) ----
    #pragma unroll
    for (int s = tid; s < 256; s += BLK) {
        if (s < 240) {
            const int j = s >> 4, c = s & 15;
            float m1 = 0.f, m2 = 0.f;
            #pragma unroll
            for (int p = 0; p < C_; p++) {
                float2 L = sLam[j][p];
                float msk = sMask[p];
                float crr = Cre[c * C_ + p] * msk;
                float cii = Cim[c * C_ + p] * msk;
                float a1r = sP1r[p] * L.x - sP1i[p] * L.y;
                float a1i = sP1r[p] * L.y + sP1i[p] * L.x;
                m1 = fmaf(a1r, crr, fmaf(-a1i, cii, m1));
                float a2r = sP2r[p] * L.x - sP2i[p] * L.y;
                float a2i = sP2r[p] * L.y + sP2i[p] * L.x;
                m2 = fmaf(a2r, crr, fmaf(-a2i, cii, m2));
            }
            const int base = j * 32 + ((c >> 1) << 2) + (c & 1);
            ((float*)sM)[base]     = m1;
            ((float*)sM)[base + 2] = m2;
        } else {
            const int c = s - 240;
            float k3 = 0.f;
            #pragma unroll
            for (int p = 0; p < C_; p++) {
                float msk = sMask[p];
                k3 = fmaf(sQ3r[p], Cre[c * C_ + p] * msk,
                     fmaf(-sQ3i[p], Cim[c * C_ + p] * msk, k3));
            }
            sK3[c] = k3;
        }
    }
    __syncthreads();

    const int n  = blockIdx.x * BLK + tid;
    const int b  = n / HW_;
    const int hw = n - b * HW_;
    const float* xp = x + (size_t)b * (T_ * HW_) + hw;

    // prefetch all T inputs (coalesced, MLP=15)
    float xv[T_];
    #pragma unroll
    for (int t = 0; t < T_; t++) xv[t] = __ldg(xp + t * HW_);

    const float varA = sVarA, varB2 = sVarB2, varC = sVarC;

    // y accumulators over c-pairs, init with K3
    u64 yacc[KP];
    #pragma unroll
    for (int k = 0; k < KP; k++) yacc[k] = ldsh(((const float2*)sK3)[k]);

    float rl = 0.f;
    #pragma unroll
    for (int t = 0; t < T_; t++) {
        const int j = T_ - 1 - t;
        float xt = xv[t];
        float var = fmaf(xt, fmaf(xt, varA, varB2), varC);
        float r = rsqrtf(var + EPS_);
        if (t == T_ - 1) rl = r;
        u64 s1v = pk2(r * xt, r * xt);
        u64 s0v = pk2(r, r);
        #pragma unroll
        for (int k = 0; k < KP; k++) {
            float4 M = sM[j][k];
            yacc[k] = ffma2(s1v, pk2(M.x, M.y), ffma2(s0v, pk2(M.z, M.w), yacc[k]));
        }
    }

    // ---- t = T-1 only from here on ----
    const float xl = xv[T_ - 1];
    float z[C_];
    #pragma unroll
    for (int k = 0; k < KP; k++) {
        float2 yk = upk(yacc[k]);
        #pragma unroll
        for (int h = 0; h < 2; h++) {
            int c = 2 * k + h;
            float yc = (h == 0) ? yk.x : yk.y;
            float fx = fmaf(fmaf(xl, sWc[c], sBc[c]) * rl, sG1[c], sB1[c]);
            yc = fmaf(fx, sD[c], yc);
            z[c] = gelu_exact(yc) + fx;
        }
    }

    // LN(z) -> fx2
    float mu = 0.f;
    #pragma unroll
    for (int c = 0; c < C_; c++) mu += z[c];
    mu *= (1.f / C_);
    float vv = 0.f;
    #pragma unroll
    for (int c = 0; c < C_; c++) { float d = z[c] - mu; vv = fmaf(d, d, vv); }
    float rs = rsqrtf(vv * (1.f / C_) + EPS_);
    float fx2s[C_];
    #pragma unroll
    for (int c = 0; c < C_; c++) fx2s[c] = fmaf((z[c] - mu) * rs, sFfg[c], sFfb[c]);

    u64 f2p[KP];
    #pragma unroll
    for (int k = 0; k < KP; k++) f2p[k] = pk2(fx2s[2 * k], fx2s[2 * k + 1]);

    // enc = fx2 @ We^T ; h = a * gelu(g)
    float av[C_];
    #pragma unroll
    for (int j = 0; j < C_; j++) {
        u64 acc = 0ull;
        #pragma unroll
        for (int q = 0; q < 4; q++) {
            float4 w = sWe4[j][q];
            acc = ffma2(f2p[2 * q],     pk2(w.x, w.y), acc);
            acc = ffma2(f2p[2 * q + 1], pk2(w.z, w.w), acc);
        }
        av[j] = hadd(acc);
    }
    float hv[C_];
    #pragma unroll
    for (int j = 0; j < C_; j++) {
        u64 acc = 0ull;
        #pragma unroll
        for (int q = 0; q < 4; q++) {
            float4 w = sWe4[C_ + j][q];
            acc = ffma2(f2p[2 * q],     pk2(w.x, w.y), acc);
            acc = ffma2(f2p[2 * q + 1], pk2(w.z, w.w), acc);
        }
        hv[j] = av[j] * gelu_exact(hadd(acc));
    }
    u64 hp[KP];
    #pragma unroll
    for (int k = 0; k < KP; k++) hp[k] = pk2(hv[2 * k], hv[2 * k + 1]);

    // z2 = h @ Wd^T + fx2
    float z2[C_];
    #pragma unroll
    for (int c = 0; c < C_; c++) {
        u64 acc = 0ull;
        #pragma unroll
        for (int q = 0; q < 4; q++) {
            float4 w = sWd4[c][q];
            acc = ffma2(hp[2 * q],     pk2(w.x, w.y), acc);
            acc = ffma2(hp[2 * q + 1], pk2(w.z, w.w), acc);
        }
        z2[c] = hadd(acc) + fx2s[c];
    }

    // LN(z2) -> v ; out = v @ Wo^T + b_out
    float mu2 = 0.f;
    #pragma unroll
    for (int c = 0; c < C_; c++) mu2 += z2[c];
    mu2 *= (1.f / C_);
    float vv2 = 0.f;
    #pragma unroll
    for (int c = 0; c < C_; c++) { float d = z2[c] - mu2; vv2 = fmaf(d, d, vv2); }
    float rs2 = rsqrtf(vv2 * (1.f / C_) + EPS_);
    u64 vp[KP];
    #pragma unroll
    for (int k = 0; k < KP; k++) {
        float v0 = fmaf((z2[2 * k]     - mu2) * rs2, sOg[2 * k],     sOb[2 * k]);
        float v1 = fmaf((z2[2 * k + 1] - mu2) * rs2, sOg[2 * k + 1], sOb[2 * k + 1]);
        vp[k] = pk2(v0, v1);
    }

    float* op = out + (size_t)b * (C_ * HW_) + hw;
    #pragma unroll
    for (int c = 0; c < C_; c++) {
        u64 acc = 0ull;
        #pragma unroll
        for (int q = 0; q < 4; q++) {
            float4 w = sWo4[c][q];
            acc = ffma2(vp[2 * q],     pk2(w.x, w.y), acc);
            acc = ffma2(vp[2 * q + 1], pk2(w.z, w.w), acc);
        }
        op[c * HW_] = hadd(acc) + sBo[c];
    }
}

extern "C" void kernel_launch(void* const* d_in, const int* in_sizes, int n_in,
                              void* d_out, int out_size)
{
    const float* x     = (const float*)d_in[0];
    const float* w_in  = (const float*)d_in[1];
    const float* b_in  = (const float*)d_in[2];
    const float* ag    = (const float*)d_in[3];
    const float* ab    = (const float*)d_in[4];
    const float* Lre   = (const float*)d_in[5];
    const float* Lim   = (const float*)d_in[6];
    const float* Bre   = (const float*)d_in[7];
    const float* Bim   = (const float*)d_in[8];
    const float* Cre   = (const float*)d_in[9];
    const float* Cim   = (const float*)d_in[10];
    const float* Dv    = (const float*)d_in[11];
    const float* lstep = (const float*)d_in[12];
    const float* ffg   = (const float*)d_in[13];
    const float* ffb   = (const float*)d_in[14];
    const float* We    = (const float*)d_in[15];
    const float* Wd    = (const float*)d_in[16];
    const float* og    = (const float*)d_in[17];
    const float* ob    = (const float*)d_in[18];
    const float* Wo    = (const float*)d_in[19];
    const float* bo    = (const float*)d_in[20];

    ssm_kernel<<<NSEQ / BLK, BLK>>>(x, w_in, b_in, ag, ab, Lre, Lim, Bre, Bim,
                                    Cre, Cim, Dv, lstep, ffg, ffb, We, Wd,
                                    og, ob, Wo, bo, (float*)d_out);
}